// round 12
// baseline (speedup 1.0000x reference)
#include <cuda_runtime.h>
#include <cuda_bf16.h>
#include <cstdint>

// ---------------------------------------------------------------------------
// DrugEmbed: GCNConv(128->128) -> BN -> ReLU -> GCNConv(128->100) -> seg-max
// R12: R11 + quad-node-per-warp aggregation (4 independent gather chains,
//      MLP~8). GEMM unchanged (persistent, 64-row tile, 2 CTAs/SM,
//      direct-store epilogue).
// ---------------------------------------------------------------------------

#define NMAX 200000
#define EMAX 600000
#define DH   128
#define NSM  148

__device__ __align__(16) float g_bufA[(size_t)NMAX * DH];
__device__ __align__(16) float g_bufB[(size_t)NMAX * DH];
__device__ int   g_cnt[NMAX];
__device__ int   g_base[NMAX];
__device__ int   g_cursor[NMAX];
__device__ int   g_csrc[EMAX];
__device__ int   g_bsum[1024];
__device__ float g_dinv[NMAX];
__device__ __align__(16) float g_bnsum[DH];
__device__ __align__(16) float g_bnsumsq[DH];
__device__ __align__(16) float g_bnscale[DH];
__device__ __align__(16) float g_bnshift[DH];

// ------------------------------ helpers -----------------------------------
__device__ __forceinline__ uint32_t smem_u32(const void* p) {
    uint32_t a;
    asm("{ .reg .u64 t; cvta.to.shared.u64 t, %1; cvt.u32.u64 %0, t; }"
        : "=r"(a) : "l"(p));
    return a;
}
__device__ __forceinline__ void ldmx4(uint32_t* r, uint32_t addr) {
    asm volatile("ldmatrix.sync.aligned.m8n8.x4.shared.b16 {%0,%1,%2,%3}, [%4];"
                 : "=r"(r[0]), "=r"(r[1]), "=r"(r[2]), "=r"(r[3]) : "r"(addr));
}
__device__ __forceinline__ void ldmx4t(uint32_t* r, uint32_t addr) {
    asm volatile("ldmatrix.sync.aligned.m8n8.x4.trans.shared.b16 {%0,%1,%2,%3}, [%4];"
                 : "=r"(r[0]), "=r"(r[1]), "=r"(r[2]), "=r"(r[3]) : "r"(addr));
}
__device__ __forceinline__ void mma_bf16(float* d, const uint32_t* a,
                                         uint32_t b0, uint32_t b1) {
    asm volatile(
        "mma.sync.aligned.m16n8k16.row.col.f32.bf16.bf16.f32 "
        "{%0,%1,%2,%3}, {%4,%5,%6,%7}, {%8,%9}, {%0,%1,%2,%3};"
        : "+f"(d[0]), "+f"(d[1]), "+f"(d[2]), "+f"(d[3])
        : "r"(a[0]), "r"(a[1]), "r"(a[2]), "r"(a[3]), "r"(b0), "r"(b1));
}
__device__ __forceinline__ void split8(const float* f, uint4* hiOut, uint4* loOut) {
    __align__(16) __nv_bfloat16 hi8[8], lo8[8];
    #pragma unroll
    for (int j = 0; j < 8; ++j) {
        __nv_bfloat16 h = __float2bfloat16_rn(f[j]);
        hi8[j] = h;
        lo8[j] = __float2bfloat16_rn(f[j] - __bfloat162float(h));
    }
    *hiOut = *reinterpret_cast<const uint4*>(hi8);
    *loOut = *reinterpret_cast<const uint4*>(lo8);
}
__device__ __forceinline__ void atomicMaxF(float* addr, float v) {
    if (v >= 0.0f) atomicMax(reinterpret_cast<int*>(addr), __float_as_int(v));
    else           atomicMin(reinterpret_cast<unsigned int*>(addr), __float_as_uint(v));
}
__device__ __forceinline__ void add4(float4& a, const float4& b) {
    a.x += b.x; a.y += b.y; a.z += b.z; a.w += b.w;
}

// ---------------------------------------------------------------------------
// prep kernels
// ---------------------------------------------------------------------------
__global__ void init_kernel(unsigned int* out, int out_n, int nrows) {
    int i = blockIdx.x * blockDim.x + threadIdx.x;
    if (i < nrows) g_cnt[i] = 0;
    if (i < out_n) out[i] = 0xFF800000u;  // -inf
    if (i < DH) { g_bnsum[i] = 0.0f; g_bnsumsq[i] = 0.0f; }
}
__global__ void deg_kernel(const int* __restrict__ dst, int E) {
    int e = blockIdx.x * blockDim.x + threadIdx.x;
    if (e < E) atomicAdd(&g_cnt[dst[e]], 1);
}
__global__ void scan1_kernel(int n) {
    __shared__ int sh[256];
    int tid = threadIdx.x;
    int i = blockIdx.x * 256 + tid;
    int v = (i < n) ? g_cnt[i] : 0;
    if (i < n) {
        g_dinv[i] = rsqrtf((float)(v + 1));
        g_cursor[i] = 0;
    }
    sh[tid] = v;
    __syncthreads();
    #pragma unroll
    for (int off = 1; off < 256; off <<= 1) {
        int t = (tid >= off) ? sh[tid - off] : 0;
        __syncthreads();
        sh[tid] += t;
        __syncthreads();
    }
    if (i < n) g_base[i] = sh[tid] - v;
    if (tid == 255) g_bsum[blockIdx.x] = sh[255];
}
__global__ void scan2_kernel(int nb) {
    __shared__ int sh[1024];
    int tid = threadIdx.x;
    int v = (tid < nb) ? g_bsum[tid] : 0;
    sh[tid] = v;
    __syncthreads();
    #pragma unroll
    for (int off = 1; off < 1024; off <<= 1) {
        int t = (tid >= off) ? sh[tid - off] : 0;
        __syncthreads();
        sh[tid] += t;
        __syncthreads();
    }
    if (tid < nb) g_bsum[tid] = sh[tid] - v;
}
__global__ void scan3_kernel(int n) {
    int i = blockIdx.x * blockDim.x + threadIdx.x;
    if (i < n) g_base[i] += g_bsum[blockIdx.x];
}
__global__ void scatter_kernel(const int* __restrict__ src,
                               const int* __restrict__ dst, int E) {
    int e = blockIdx.x * blockDim.x + threadIdx.x;
    if (e >= E) return;
    int d = dst[e];
    int pos = atomicAdd(&g_cursor[d], 1);
    g_csrc[g_base[d] + pos] = src[e];
}

// ---------------------------------------------------------------------------
// Persistent tensor-core GEMM (unchanged from R11).
// ---------------------------------------------------------------------------
template<int NCOLS, bool APPLY_BN, bool A_INTERNAL>
__global__ void __launch_bounds__(256, 2)
gemm_mma_kernel(const float* Aext, const float* __restrict__ W, int nrows)
{
    extern __shared__ char smem[];
    const int LDA = 272;
    char* AhiP = smem;                  // 64 x 272 = 17408
    char* AloP = smem + 17408;
    char* WhiP = smem + 34816;          // 128 x 272 = 34816
    char* WloP = smem + 69632;

    const int tid  = threadIdx.x;
    const int lane = tid & 31;
    const int wid  = tid >> 5;

    const float* A = A_INTERNAL ? g_bufB : Aext;
    float* outG    = g_bufA;

    // ---- stage W once ----
    #pragma unroll
    for (int it = 0; it < 8; ++it) {
        int o  = tid + it * 256;
        int k  = o >> 4;
        int n0 = (o & 15) << 3;
        float f[8];
        if (NCOLS == 128) {
            float4 v0 = *reinterpret_cast<const float4*>(&W[(size_t)k * 128 + n0]);
            float4 v1 = *reinterpret_cast<const float4*>(&W[(size_t)k * 128 + n0 + 4]);
            f[0]=v0.x; f[1]=v0.y; f[2]=v0.z; f[3]=v0.w;
            f[4]=v1.x; f[5]=v1.y; f[6]=v1.z; f[7]=v1.w;
        } else {
            #pragma unroll
            for (int j = 0; j < 8; ++j)
                f[j] = (n0 + j < NCOLS) ? W[(size_t)k * NCOLS + n0 + j] : 0.0f;
        }
        uint4 hi, lo;
        split8(f, &hi, &lo);
        *reinterpret_cast<uint4*>(WhiP + k * LDA + n0 * 2) = hi;
        *reinterpret_cast<uint4*>(WloP + k * LDA + n0 * 2) = lo;
    }

    const int wm   = (wid & 1) << 5;
    const int wn   = (wid >> 1) << 5;
    const int lrow = lane & 15;
    const int lc8  = (lane >> 4) << 3;
    const int qr   = lane >> 2;
    const int qc   = (lane & 3) << 1;
    const uint32_t sAhi = smem_u32(AhiP), sAlo = smem_u32(AloP);
    const uint32_t sWhi = smem_u32(WhiP), sWlo = smem_u32(WloP);
    const int NPAD = (NCOLS + 7) & ~7;
    const int ntiles = (nrows + 63) >> 6;

    for (int tile = blockIdx.x; tile < ntiles; tile += gridDim.x) {
        const int row0 = tile << 6;

        // ---- stage A rows ----
        #pragma unroll
        for (int it = 0; it < 4; ++it) {
            int o  = tid + it * 256;
            int m  = o >> 4;
            int k0 = (o & 15) << 3;
            int grow = row0 + m;
            float4 v0 = make_float4(0.f, 0.f, 0.f, 0.f), v1 = v0;
            if (grow < nrows) {
                v0 = *reinterpret_cast<const float4*>(&A[(size_t)grow * 128 + k0]);
                v1 = *reinterpret_cast<const float4*>(&A[(size_t)grow * 128 + k0 + 4]);
            }
            float f[8] = {v0.x, v0.y, v0.z, v0.w, v1.x, v1.y, v1.z, v1.w};
            if (APPLY_BN) {
                float4 s0 = *reinterpret_cast<const float4*>(&g_bnscale[k0]);
                float4 s1 = *reinterpret_cast<const float4*>(&g_bnscale[k0 + 4]);
                float4 t0 = *reinterpret_cast<const float4*>(&g_bnshift[k0]);
                float4 t1 = *reinterpret_cast<const float4*>(&g_bnshift[k0 + 4]);
                float sc[8] = {s0.x, s0.y, s0.z, s0.w, s1.x, s1.y, s1.z, s1.w};
                float sh[8] = {t0.x, t0.y, t0.z, t0.w, t1.x, t1.y, t1.z, t1.w};
                #pragma unroll
                for (int j = 0; j < 8; ++j)
                    f[j] = fmaxf(fmaf(f[j], sc[j], sh[j]), 0.f);
            }
            uint4 hi, lo;
            split8(f, &hi, &lo);
            *reinterpret_cast<uint4*>(AhiP + m * LDA + k0 * 2) = hi;
            *reinterpret_cast<uint4*>(AloP + m * LDA + k0 * 2) = lo;
        }
        __syncthreads();

        // ---- mma mainloop ----
        float acc[2][4][4];
        #pragma unroll
        for (int mt = 0; mt < 2; ++mt)
            #pragma unroll
            for (int nt = 0; nt < 4; ++nt)
                #pragma unroll
                for (int j = 0; j < 4; ++j) acc[mt][nt][j] = 0.0f;

        #pragma unroll
        for (int term = 0; term < 3; ++term) {
            const uint32_t aB = (term == 2) ? sAlo : sAhi;
            const uint32_t bB = (term == 1) ? sWlo : sWhi;
            const uint32_t aAddr0 = aB + (wm + lrow) * LDA + lc8 * 2;
            const uint32_t aAddr1 = aAddr0 + 16 * LDA;
            const uint32_t bAddr  = bB + lrow * LDA + (wn + lc8) * 2;
            #pragma unroll
            for (int ks = 0; ks < 8; ++ks) {
                uint32_t a0[4], a1[4];
                ldmx4(a0, aAddr0 + ks * 32);
                ldmx4(a1, aAddr1 + ks * 32);
                #pragma unroll
                for (int nt2 = 0; nt2 < 2; ++nt2) {
                    if (wn + nt2 * 16 >= NPAD) break;
                    uint32_t b[4];
                    ldmx4t(b, bAddr + ks * 16 * LDA + nt2 * 32);
                    mma_bf16(acc[0][2 * nt2 + 0], a0, b[0], b[1]);
                    mma_bf16(acc[0][2 * nt2 + 1], a0, b[2], b[3]);
                    mma_bf16(acc[1][2 * nt2 + 0], a1, b[0], b[1]);
                    mma_bf16(acc[1][2 * nt2 + 1], a1, b[2], b[3]);
                }
            }
        }
        __syncthreads();

        // ---- epilogue: direct float2 stores ----
        #pragma unroll
        for (int mt = 0; mt < 2; ++mt) {
            int r_lo = wm + mt * 16 + qr;
            int r_hi = r_lo + 8;
            int g_lo = row0 + r_lo, g_hi = row0 + r_hi;
            float s_lo = (g_lo < nrows) ? g_dinv[g_lo] : 0.0f;
            float s_hi = (g_hi < nrows) ? g_dinv[g_hi] : 0.0f;
            #pragma unroll
            for (int nt = 0; nt < 4; ++nt) {
                int c = wn + nt * 8 + qc;
                if (NCOLS < 128 && c >= NCOLS) continue;
                if (g_lo < nrows) {
                    float2 v = make_float2(acc[mt][nt][0] * s_lo,
                                           acc[mt][nt][1] * s_lo);
                    *reinterpret_cast<float2*>(&outG[(size_t)g_lo * 128 + c]) = v;
                }
                if (g_hi < nrows) {
                    float2 v = make_float2(acc[mt][nt][2] * s_hi,
                                           acc[mt][nt][3] * s_hi);
                    *reinterpret_cast<float2*>(&outG[(size_t)g_hi * 128 + c]) = v;
                }
            }
        }
    }
}

// ---------------------------------------------------------------------------
// agg1: warp handles FOUR nodes (4 independent chains x 2-unroll, MLP~8).
// x1 = (h'[n] + sum h'[src]) * dinv[n] + b1 -> g_bufB; BN stats pre-summed.
// ---------------------------------------------------------------------------
__global__ void __launch_bounds__(256)
agg1_kernel(const float* __restrict__ b1, int nrows)
{
    __shared__ float ssum[128];
    __shared__ float ssq[128];
    const int tid  = threadIdx.x;
    const int wid  = tid >> 5;
    const int lane = tid & 31;
    if (tid < 128) { ssum[tid] = 0.0f; ssq[tid] = 0.0f; }
    __syncthreads();

    const int nb = (blockIdx.x * 8 + wid) * 4;
    const int c4 = lane << 2;
    const float* gb = g_bufA;

    float4 Aacc[4], Bacc[4];
    int s[4], nc[4];
    int mx = 0;
    #pragma unroll
    for (int q = 0; q < 4; ++q) {
        int n = nb + q;
        bool v = n < nrows;
        s[q]  = v ? g_base[n] : 0;
        nc[q] = v ? g_cnt[n]  : 0;
        Aacc[q] = v ? *reinterpret_cast<const float4*>(&gb[(size_t)n * 128 + c4])
                    : make_float4(0.f, 0.f, 0.f, 0.f);
        Bacc[q] = make_float4(0.f, 0.f, 0.f, 0.f);
        if (nc[q] > mx) mx = nc[q];
    }

    for (int i = 0; i < mx; i += 2) {
        #pragma unroll
        for (int q = 0; q < 4; ++q) {
            if (i < nc[q]) {
                int sa = __ldg(&g_csrc[s[q] + i]);
                add4(Aacc[q], *reinterpret_cast<const float4*>(&gb[(size_t)sa * 128 + c4]));
            }
            if (i + 1 < nc[q]) {
                int sb = __ldg(&g_csrc[s[q] + i + 1]);
                add4(Bacc[q], *reinterpret_cast<const float4*>(&gb[(size_t)sb * 128 + c4]));
            }
        }
    }

    float4 bb = *reinterpret_cast<const float4*>(&b1[c4]);
    float4 st = make_float4(0.f, 0.f, 0.f, 0.f), sq = st;
    #pragma unroll
    for (int q = 0; q < 4; ++q) {
        int n = nb + q;
        if (n >= nrows) continue;
        add4(Aacc[q], Bacc[q]);
        float di = g_dinv[n];
        float4 v = make_float4(fmaf(Aacc[q].x, di, bb.x), fmaf(Aacc[q].y, di, bb.y),
                               fmaf(Aacc[q].z, di, bb.z), fmaf(Aacc[q].w, di, bb.w));
        *reinterpret_cast<float4*>(&g_bufB[(size_t)n * 128 + c4]) = v;
        st.x += v.x; st.y += v.y; st.z += v.z; st.w += v.w;
        sq.x += v.x*v.x; sq.y += v.y*v.y; sq.z += v.z*v.z; sq.w += v.w*v.w;
    }
    if (nb < nrows) {
        atomicAdd(&ssum[c4 + 0], st.x); atomicAdd(&ssq[c4 + 0], sq.x);
        atomicAdd(&ssum[c4 + 1], st.y); atomicAdd(&ssq[c4 + 1], sq.y);
        atomicAdd(&ssum[c4 + 2], st.z); atomicAdd(&ssq[c4 + 2], sq.z);
        atomicAdd(&ssum[c4 + 3], st.w); atomicAdd(&ssq[c4 + 3], sq.w);
    }
    __syncthreads();
    if (tid < 128) {
        atomicAdd(&g_bnsum[tid],   ssum[tid]);
        atomicAdd(&g_bnsumsq[tid], ssq[tid]);
    }
}

__global__ void bn_params_kernel(const float* __restrict__ gamma,
                                 const float* __restrict__ beta, float inv_n)
{
    int c = threadIdx.x;
    float mean = g_bnsum[c] * inv_n;
    float var  = fmaxf(g_bnsumsq[c] * inv_n - mean * mean, 0.0f);
    float sc   = gamma[c] * rsqrtf(var + 1e-5f);
    g_bnscale[c] = sc;
    g_bnshift[c] = beta[c] - mean * sc;
}

// ---------------------------------------------------------------------------
// agg2: warp handles FOUR nodes; fused dinv+bias+global max pool (100 cols).
// Index loads uniform (all lanes); row loads by lanes 0..24.
// ---------------------------------------------------------------------------
__global__ void __launch_bounds__(256)
agg2_kernel(const float* __restrict__ b2, const int* __restrict__ batch,
            float* out, int nrows)
{
    const int tid  = threadIdx.x;
    const int wid  = tid >> 5;
    const int lane = tid & 31;
    const int nb = (blockIdx.x * 8 + wid) * 4;
    if (nb >= nrows) return;
    const bool active = (lane < 25);
    const int c4 = lane << 2;
    const float* gb = g_bufA;

    float4 Aacc[4], Bacc[4];
    int s[4], nc[4];
    int mx = 0;
    #pragma unroll
    for (int q = 0; q < 4; ++q) {
        int n = nb + q;
        bool v = n < nrows;
        s[q]  = v ? g_base[n] : 0;
        nc[q] = v ? g_cnt[n]  : 0;
        Aacc[q] = (v && active)
                  ? *reinterpret_cast<const float4*>(&gb[(size_t)n * 128 + c4])
                  : make_float4(0.f, 0.f, 0.f, 0.f);
        Bacc[q] = make_float4(0.f, 0.f, 0.f, 0.f);
        if (nc[q] > mx) mx = nc[q];
    }

    for (int i = 0; i < mx; i += 2) {
        #pragma unroll
        for (int q = 0; q < 4; ++q) {
            if (i < nc[q]) {
                int sa = __ldg(&g_csrc[s[q] + i]);
                if (active)
                    add4(Aacc[q], *reinterpret_cast<const float4*>(&gb[(size_t)sa * 128 + c4]));
            }
            if (i + 1 < nc[q]) {
                int sb = __ldg(&g_csrc[s[q] + i + 1]);
                if (active)
                    add4(Bacc[q], *reinterpret_cast<const float4*>(&gb[(size_t)sb * 128 + c4]));
            }
        }
    }
    if (!active) return;

    float4 bb = *reinterpret_cast<const float4*>(&b2[c4]);
    #pragma unroll
    for (int q = 0; q < 4; ++q) {
        int n = nb + q;
        if (n >= nrows) continue;
        add4(Aacc[q], Bacc[q]);
        int g = __ldg(&batch[n]);
        float di = g_dinv[n];
        float* op = &out[(size_t)g * 100 + c4];
        atomicMaxF(op + 0, fmaf(Aacc[q].x, di, bb.x));
        atomicMaxF(op + 1, fmaf(Aacc[q].y, di, bb.y));
        atomicMaxF(op + 2, fmaf(Aacc[q].z, di, bb.z));
        atomicMaxF(op + 3, fmaf(Aacc[q].w, di, bb.w));
    }
}

// ---------------------------------------------------------------------------
extern "C" void kernel_launch(void* const* d_in, const int* in_sizes, int n_in,
                              void* d_out, int out_size)
{
    const float* atom  = (const float*)d_in[0];
    const int*   eidx  = (const int*)d_in[1];
    const int*   batch = (const int*)d_in[2];

    int base = 3;
    if (n_in >= 10 && in_sizes[3] == 1) base = 4;
    const float* W1    = (const float*)d_in[base + 0];
    const float* b1    = (const float*)d_in[base + 1];
    const float* gamma = (const float*)d_in[base + 2];
    const float* beta  = (const float*)d_in[base + 3];
    const float* W2    = (const float*)d_in[base + 4];
    const float* b2    = (const float*)d_in[base + 5];

    const int N = in_sizes[2];
    const int E = in_sizes[1] / 2;
    const int* src = eidx;
    const int* dst = eidx + E;
    float* out = (float*)d_out;

    const int SMEM_BYTES = 104448;  // 2*17408 + 2*34816
    static bool attr_done = false;
    if (!attr_done) {
        cudaFuncSetAttribute(gemm_mma_kernel<128, false, false>,
                             cudaFuncAttributeMaxDynamicSharedMemorySize, SMEM_BYTES);
        cudaFuncSetAttribute(gemm_mma_kernel<100, true, true>,
                             cudaFuncAttributeMaxDynamicSharedMemorySize, SMEM_BYTES);
        attr_done = true;
    }

    const int nScanBlocks = (N + 255) / 256;
    const int initN = (N > out_size) ? N : out_size;

    init_kernel<<<(initN + 255) / 256, 256>>>((unsigned int*)d_out, out_size, N);
    deg_kernel<<<(E + 255) / 256, 256>>>(dst, E);
    scan1_kernel<<<nScanBlocks, 256>>>(N);
    scan2_kernel<<<1, 1024>>>(nScanBlocks);
    scan3_kernel<<<nScanBlocks, 256>>>(N);
    scatter_kernel<<<(E + 255) / 256, 256>>>(src, dst, E);

    const int ablocks = (N + 31) / 32;   // 32 nodes per block (4 per warp)
    const int GGRID = 2 * NSM;           // 2 CTAs per SM

    // Layer 1
    gemm_mma_kernel<128, false, false><<<GGRID, 256, SMEM_BYTES>>>(atom, W1, N);
    agg1_kernel<<<ablocks, 256>>>(b1, N);
    bn_params_kernel<<<1, 128>>>(gamma, beta, 1.0f / (float)N);

    // Layer 2
    gemm_mma_kernel<100, true, true><<<GGRID, 256, SMEM_BYTES>>>(nullptr, W2, N);
    agg2_kernel<<<ablocks, 256>>>(b2, batch, out, N);
}

// round 13
// speedup vs baseline: 1.0937x; 1.0937x over previous
#include <cuda_runtime.h>
#include <cuda_bf16.h>
#include <cstdint>

// ---------------------------------------------------------------------------
// DrugEmbed: GCNConv(128->128) -> BN -> ReLU -> GCNConv(128->100) -> seg-max
// R13: R11 aggs (dual-node per warp — R12 quad-node was neutral/worse).
//      GEMM mainloop restructured to single k-pass over all 3 split terms:
//      a_hi/a_lo and b_hi/b_lo each loaded ONCE per k-step (LDSM -33%).
// ---------------------------------------------------------------------------

#define NMAX 200000
#define EMAX 600000
#define DH   128
#define NSM  148

__device__ __align__(16) float g_bufA[(size_t)NMAX * DH];
__device__ __align__(16) float g_bufB[(size_t)NMAX * DH];
__device__ int   g_cnt[NMAX];
__device__ int   g_base[NMAX];
__device__ int   g_cursor[NMAX];
__device__ int   g_csrc[EMAX];
__device__ int   g_bsum[1024];
__device__ float g_dinv[NMAX];
__device__ __align__(16) float g_bnsum[DH];
__device__ __align__(16) float g_bnsumsq[DH];
__device__ __align__(16) float g_bnscale[DH];
__device__ __align__(16) float g_bnshift[DH];

// ------------------------------ helpers -----------------------------------
__device__ __forceinline__ uint32_t smem_u32(const void* p) {
    uint32_t a;
    asm("{ .reg .u64 t; cvta.to.shared.u64 t, %1; cvt.u32.u64 %0, t; }"
        : "=r"(a) : "l"(p));
    return a;
}
__device__ __forceinline__ void ldmx4(uint32_t* r, uint32_t addr) {
    asm volatile("ldmatrix.sync.aligned.m8n8.x4.shared.b16 {%0,%1,%2,%3}, [%4];"
                 : "=r"(r[0]), "=r"(r[1]), "=r"(r[2]), "=r"(r[3]) : "r"(addr));
}
__device__ __forceinline__ void ldmx4t(uint32_t* r, uint32_t addr) {
    asm volatile("ldmatrix.sync.aligned.m8n8.x4.trans.shared.b16 {%0,%1,%2,%3}, [%4];"
                 : "=r"(r[0]), "=r"(r[1]), "=r"(r[2]), "=r"(r[3]) : "r"(addr));
}
__device__ __forceinline__ void mma_bf16(float* d, const uint32_t* a,
                                         uint32_t b0, uint32_t b1) {
    asm volatile(
        "mma.sync.aligned.m16n8k16.row.col.f32.bf16.bf16.f32 "
        "{%0,%1,%2,%3}, {%4,%5,%6,%7}, {%8,%9}, {%0,%1,%2,%3};"
        : "+f"(d[0]), "+f"(d[1]), "+f"(d[2]), "+f"(d[3])
        : "r"(a[0]), "r"(a[1]), "r"(a[2]), "r"(a[3]), "r"(b0), "r"(b1));
}
__device__ __forceinline__ void split8(const float* f, uint4* hiOut, uint4* loOut) {
    __align__(16) __nv_bfloat16 hi8[8], lo8[8];
    #pragma unroll
    for (int j = 0; j < 8; ++j) {
        __nv_bfloat16 h = __float2bfloat16_rn(f[j]);
        hi8[j] = h;
        lo8[j] = __float2bfloat16_rn(f[j] - __bfloat162float(h));
    }
    *hiOut = *reinterpret_cast<const uint4*>(hi8);
    *loOut = *reinterpret_cast<const uint4*>(lo8);
}
__device__ __forceinline__ void atomicMaxF(float* addr, float v) {
    if (v >= 0.0f) atomicMax(reinterpret_cast<int*>(addr), __float_as_int(v));
    else           atomicMin(reinterpret_cast<unsigned int*>(addr), __float_as_uint(v));
}
__device__ __forceinline__ void add4(float4& a, const float4& b) {
    a.x += b.x; a.y += b.y; a.z += b.z; a.w += b.w;
}

// ---------------------------------------------------------------------------
// prep kernels
// ---------------------------------------------------------------------------
__global__ void init_kernel(unsigned int* out, int out_n, int nrows) {
    int i = blockIdx.x * blockDim.x + threadIdx.x;
    if (i < nrows) g_cnt[i] = 0;
    if (i < out_n) out[i] = 0xFF800000u;  // -inf
    if (i < DH) { g_bnsum[i] = 0.0f; g_bnsumsq[i] = 0.0f; }
}
__global__ void deg_kernel(const int* __restrict__ dst, int E) {
    int e = blockIdx.x * blockDim.x + threadIdx.x;
    if (e < E) atomicAdd(&g_cnt[dst[e]], 1);
}
__global__ void scan1_kernel(int n) {
    __shared__ int sh[256];
    int tid = threadIdx.x;
    int i = blockIdx.x * 256 + tid;
    int v = (i < n) ? g_cnt[i] : 0;
    if (i < n) {
        g_dinv[i] = rsqrtf((float)(v + 1));
        g_cursor[i] = 0;
    }
    sh[tid] = v;
    __syncthreads();
    #pragma unroll
    for (int off = 1; off < 256; off <<= 1) {
        int t = (tid >= off) ? sh[tid - off] : 0;
        __syncthreads();
        sh[tid] += t;
        __syncthreads();
    }
    if (i < n) g_base[i] = sh[tid] - v;
    if (tid == 255) g_bsum[blockIdx.x] = sh[255];
}
__global__ void scan2_kernel(int nb) {
    __shared__ int sh[1024];
    int tid = threadIdx.x;
    int v = (tid < nb) ? g_bsum[tid] : 0;
    sh[tid] = v;
    __syncthreads();
    #pragma unroll
    for (int off = 1; off < 1024; off <<= 1) {
        int t = (tid >= off) ? sh[tid - off] : 0;
        __syncthreads();
        sh[tid] += t;
        __syncthreads();
    }
    if (tid < nb) g_bsum[tid] = sh[tid] - v;
}
__global__ void scan3_kernel(int n) {
    int i = blockIdx.x * blockDim.x + threadIdx.x;
    if (i < n) g_base[i] += g_bsum[blockIdx.x];
}
__global__ void scatter_kernel(const int* __restrict__ src,
                               const int* __restrict__ dst, int E) {
    int e = blockIdx.x * blockDim.x + threadIdx.x;
    if (e >= E) return;
    int d = dst[e];
    int pos = atomicAdd(&g_cursor[d], 1);
    g_csrc[g_base[d] + pos] = src[e];
}

// ---------------------------------------------------------------------------
// Persistent tensor-core GEMM: C[nrows, NCOLS] = A[nrows,128] @ W[128,NCOLS]
// bf16 split D = Ahi@Whi + Ahi@Wlo + Alo@Whi, computed in ONE k-pass:
// per k-step, a_hi/a_lo and b_hi/b_lo are each loaded once, then the three
// term-MMAs issue back-to-back from registers.
// Tile = 64 rows. 8 warps (2m x 4n), warp tile 32x32. 2 CTAs/SM.
// ---------------------------------------------------------------------------
template<int NCOLS, bool APPLY_BN, bool A_INTERNAL>
__global__ void __launch_bounds__(256, 2)
gemm_mma_kernel(const float* Aext, const float* __restrict__ W, int nrows)
{
    extern __shared__ char smem[];
    const int LDA = 272;
    char* AhiP = smem;                  // 64 x 272 = 17408
    char* AloP = smem + 17408;
    char* WhiP = smem + 34816;          // 128 x 272 = 34816
    char* WloP = smem + 69632;

    const int tid  = threadIdx.x;
    const int lane = tid & 31;
    const int wid  = tid >> 5;

    const float* A = A_INTERNAL ? g_bufB : Aext;
    float* outG    = g_bufA;

    // ---- stage W once ----
    #pragma unroll
    for (int it = 0; it < 8; ++it) {
        int o  = tid + it * 256;
        int k  = o >> 4;
        int n0 = (o & 15) << 3;
        float f[8];
        if (NCOLS == 128) {
            float4 v0 = *reinterpret_cast<const float4*>(&W[(size_t)k * 128 + n0]);
            float4 v1 = *reinterpret_cast<const float4*>(&W[(size_t)k * 128 + n0 + 4]);
            f[0]=v0.x; f[1]=v0.y; f[2]=v0.z; f[3]=v0.w;
            f[4]=v1.x; f[5]=v1.y; f[6]=v1.z; f[7]=v1.w;
        } else {
            #pragma unroll
            for (int j = 0; j < 8; ++j)
                f[j] = (n0 + j < NCOLS) ? W[(size_t)k * NCOLS + n0 + j] : 0.0f;
        }
        uint4 hi, lo;
        split8(f, &hi, &lo);
        *reinterpret_cast<uint4*>(WhiP + k * LDA + n0 * 2) = hi;
        *reinterpret_cast<uint4*>(WloP + k * LDA + n0 * 2) = lo;
    }

    const int wm   = (wid & 1) << 5;
    const int wn   = (wid >> 1) << 5;
    const int lrow = lane & 15;
    const int lc8  = (lane >> 4) << 3;
    const int qr   = lane >> 2;
    const int qc   = (lane & 3) << 1;
    const uint32_t sAhi = smem_u32(AhiP), sAlo = smem_u32(AloP);
    const uint32_t sWhi = smem_u32(WhiP), sWlo = smem_u32(WloP);
    const int NPAD = (NCOLS + 7) & ~7;
    const int ntiles = (nrows + 63) >> 6;

    for (int tile = blockIdx.x; tile < ntiles; tile += gridDim.x) {
        const int row0 = tile << 6;

        // ---- stage A rows (64 x 128) -> bf16 hi/lo (optionally BN+ReLU) ----
        #pragma unroll
        for (int it = 0; it < 4; ++it) {
            int o  = tid + it * 256;
            int m  = o >> 4;
            int k0 = (o & 15) << 3;
            int grow = row0 + m;
            float4 v0 = make_float4(0.f, 0.f, 0.f, 0.f), v1 = v0;
            if (grow < nrows) {
                v0 = *reinterpret_cast<const float4*>(&A[(size_t)grow * 128 + k0]);
                v1 = *reinterpret_cast<const float4*>(&A[(size_t)grow * 128 + k0 + 4]);
            }
            float f[8] = {v0.x, v0.y, v0.z, v0.w, v1.x, v1.y, v1.z, v1.w};
            if (APPLY_BN) {
                float4 s0 = *reinterpret_cast<const float4*>(&g_bnscale[k0]);
                float4 s1 = *reinterpret_cast<const float4*>(&g_bnscale[k0 + 4]);
                float4 t0 = *reinterpret_cast<const float4*>(&g_bnshift[k0]);
                float4 t1 = *reinterpret_cast<const float4*>(&g_bnshift[k0 + 4]);
                float sc[8] = {s0.x, s0.y, s0.z, s0.w, s1.x, s1.y, s1.z, s1.w};
                float sh[8] = {t0.x, t0.y, t0.z, t0.w, t1.x, t1.y, t1.z, t1.w};
                #pragma unroll
                for (int j = 0; j < 8; ++j)
                    f[j] = fmaxf(fmaf(f[j], sc[j], sh[j]), 0.f);
            }
            uint4 hi, lo;
            split8(f, &hi, &lo);
            *reinterpret_cast<uint4*>(AhiP + m * LDA + k0 * 2) = hi;
            *reinterpret_cast<uint4*>(AloP + m * LDA + k0 * 2) = lo;
        }
        __syncthreads();

        // ---- mma mainloop: single k-pass, 3 terms from registers ----
        float acc[2][4][4];
        #pragma unroll
        for (int mt = 0; mt < 2; ++mt)
            #pragma unroll
            for (int nt = 0; nt < 4; ++nt)
                #pragma unroll
                for (int j = 0; j < 4; ++j) acc[mt][nt][j] = 0.0f;

        {
            const uint32_t aHi0 = sAhi + (wm + lrow) * LDA + lc8 * 2;
            const uint32_t aLo0 = sAlo + (wm + lrow) * LDA + lc8 * 2;
            const uint32_t bHi0 = sWhi + lrow * LDA + (wn + lc8) * 2;
            const uint32_t bLo0 = sWlo + lrow * LDA + (wn + lc8) * 2;
            #pragma unroll
            for (int ks = 0; ks < 8; ++ks) {
                uint32_t ah0[4], ah1[4], al0[4], al1[4];
                ldmx4(ah0, aHi0 + ks * 32);
                ldmx4(ah1, aHi0 + 16 * LDA + ks * 32);
                ldmx4(al0, aLo0 + ks * 32);
                ldmx4(al1, aLo0 + 16 * LDA + ks * 32);
                #pragma unroll
                for (int nt2 = 0; nt2 < 2; ++nt2) {
                    if (wn + nt2 * 16 >= NPAD) break;
                    uint32_t bh[4], bl[4];
                    ldmx4t(bh, bHi0 + ks * 16 * LDA + nt2 * 32);
                    ldmx4t(bl, bLo0 + ks * 16 * LDA + nt2 * 32);
                    // term 0: Ahi @ Whi
                    mma_bf16(acc[0][2 * nt2 + 0], ah0, bh[0], bh[1]);
                    mma_bf16(acc[0][2 * nt2 + 1], ah0, bh[2], bh[3]);
                    mma_bf16(acc[1][2 * nt2 + 0], ah1, bh[0], bh[1]);
                    mma_bf16(acc[1][2 * nt2 + 1], ah1, bh[2], bh[3]);
                    // term 1: Ahi @ Wlo
                    mma_bf16(acc[0][2 * nt2 + 0], ah0, bl[0], bl[1]);
                    mma_bf16(acc[0][2 * nt2 + 1], ah0, bl[2], bl[3]);
                    mma_bf16(acc[1][2 * nt2 + 0], ah1, bl[0], bl[1]);
                    mma_bf16(acc[1][2 * nt2 + 1], ah1, bl[2], bl[3]);
                    // term 2: Alo @ Whi
                    mma_bf16(acc[0][2 * nt2 + 0], al0, bh[0], bh[1]);
                    mma_bf16(acc[0][2 * nt2 + 1], al0, bh[2], bh[3]);
                    mma_bf16(acc[1][2 * nt2 + 0], al1, bh[0], bh[1]);
                    mma_bf16(acc[1][2 * nt2 + 1], al1, bh[2], bh[3]);
                }
            }
        }
        __syncthreads();

        // ---- epilogue: direct float2 stores ----
        #pragma unroll
        for (int mt = 0; mt < 2; ++mt) {
            int r_lo = wm + mt * 16 + qr;
            int r_hi = r_lo + 8;
            int g_lo = row0 + r_lo, g_hi = row0 + r_hi;
            float s_lo = (g_lo < nrows) ? g_dinv[g_lo] : 0.0f;
            float s_hi = (g_hi < nrows) ? g_dinv[g_hi] : 0.0f;
            #pragma unroll
            for (int nt = 0; nt < 4; ++nt) {
                int c = wn + nt * 8 + qc;
                if (NCOLS < 128 && c >= NCOLS) continue;
                if (g_lo < nrows) {
                    float2 v = make_float2(acc[mt][nt][0] * s_lo,
                                           acc[mt][nt][1] * s_lo);
                    *reinterpret_cast<float2*>(&outG[(size_t)g_lo * 128 + c]) = v;
                }
                if (g_hi < nrows) {
                    float2 v = make_float2(acc[mt][nt][2] * s_hi,
                                           acc[mt][nt][3] * s_hi);
                    *reinterpret_cast<float2*>(&outG[(size_t)g_hi * 128 + c]) = v;
                }
            }
        }
    }
}

// ---------------------------------------------------------------------------
// agg1 (R11 version): warp handles TWO nodes (interleaved chains, MLP~4).
// ---------------------------------------------------------------------------
__global__ void __launch_bounds__(256)
agg1_kernel(const float* __restrict__ b1, int nrows)
{
    __shared__ float ssum[128];
    __shared__ float ssq[128];
    const int tid  = threadIdx.x;
    const int wid  = tid >> 5;
    const int lane = tid & 31;
    if (tid < 128) { ssum[tid] = 0.0f; ssq[tid] = 0.0f; }
    __syncthreads();

    const int n0 = (blockIdx.x * 8 + wid) * 2;
    const int n1 = n0 + 1;
    const bool v0 = n0 < nrows, v1 = n1 < nrows;
    const int c4 = lane << 2;
    const float* gb = g_bufA;

    float4 A0 = make_float4(0.f,0.f,0.f,0.f), B0 = A0, A1 = A0, B1 = A0;
    int s0 = 0, nc0 = 0, s1 = 0, nc1 = 0;
    if (v0) { s0 = g_base[n0]; nc0 = g_cnt[n0];
              A0 = *reinterpret_cast<const float4*>(&gb[(size_t)n0 * 128 + c4]); }
    if (v1) { s1 = g_base[n1]; nc1 = g_cnt[n1];
              A1 = *reinterpret_cast<const float4*>(&gb[(size_t)n1 * 128 + c4]); }

    int mx = nc0 > nc1 ? nc0 : nc1;
    for (int i = 0; i < mx; i += 2) {
        if (i < nc0) {
            int sa = __ldg(&g_csrc[s0 + i]);
            add4(A0, *reinterpret_cast<const float4*>(&gb[(size_t)sa * 128 + c4]));
        }
        if (i + 1 < nc0) {
            int sb = __ldg(&g_csrc[s0 + i + 1]);
            add4(B0, *reinterpret_cast<const float4*>(&gb[(size_t)sb * 128 + c4]));
        }
        if (i < nc1) {
            int sa = __ldg(&g_csrc[s1 + i]);
            add4(A1, *reinterpret_cast<const float4*>(&gb[(size_t)sa * 128 + c4]));
        }
        if (i + 1 < nc1) {
            int sb = __ldg(&g_csrc[s1 + i + 1]);
            add4(B1, *reinterpret_cast<const float4*>(&gb[(size_t)sb * 128 + c4]));
        }
    }
    add4(A0, B0); add4(A1, B1);

    float4 bb = *reinterpret_cast<const float4*>(&b1[c4]);
    float4 st = make_float4(0.f,0.f,0.f,0.f), sq = st;
    if (v0) {
        float di = g_dinv[n0];
        float4 v = make_float4(fmaf(A0.x, di, bb.x), fmaf(A0.y, di, bb.y),
                               fmaf(A0.z, di, bb.z), fmaf(A0.w, di, bb.w));
        *reinterpret_cast<float4*>(&g_bufB[(size_t)n0 * 128 + c4]) = v;
        st.x += v.x; st.y += v.y; st.z += v.z; st.w += v.w;
        sq.x += v.x*v.x; sq.y += v.y*v.y; sq.z += v.z*v.z; sq.w += v.w*v.w;
    }
    if (v1) {
        float di = g_dinv[n1];
        float4 v = make_float4(fmaf(A1.x, di, bb.x), fmaf(A1.y, di, bb.y),
                               fmaf(A1.z, di, bb.z), fmaf(A1.w, di, bb.w));
        *reinterpret_cast<float4*>(&g_bufB[(size_t)n1 * 128 + c4]) = v;
        st.x += v.x; st.y += v.y; st.z += v.z; st.w += v.w;
        sq.x += v.x*v.x; sq.y += v.y*v.y; sq.z += v.z*v.z; sq.w += v.w*v.w;
    }
    if (v0 || v1) {
        atomicAdd(&ssum[c4 + 0], st.x); atomicAdd(&ssq[c4 + 0], sq.x);
        atomicAdd(&ssum[c4 + 1], st.y); atomicAdd(&ssq[c4 + 1], sq.y);
        atomicAdd(&ssum[c4 + 2], st.z); atomicAdd(&ssq[c4 + 2], sq.z);
        atomicAdd(&ssum[c4 + 3], st.w); atomicAdd(&ssq[c4 + 3], sq.w);
    }
    __syncthreads();
    if (tid < 128) {
        atomicAdd(&g_bnsum[tid],   ssum[tid]);
        atomicAdd(&g_bnsumsq[tid], ssq[tid]);
    }
}

__global__ void bn_params_kernel(const float* __restrict__ gamma,
                                 const float* __restrict__ beta, float inv_n)
{
    int c = threadIdx.x;
    float mean = g_bnsum[c] * inv_n;
    float var  = fmaxf(g_bnsumsq[c] * inv_n - mean * mean, 0.0f);
    float sc   = gamma[c] * rsqrtf(var + 1e-5f);
    g_bnscale[c] = sc;
    g_bnshift[c] = beta[c] - mean * sc;
}

// ---------------------------------------------------------------------------
// agg2 (R11 version): warp handles TWO nodes; fused dinv+bias+max pool.
// ---------------------------------------------------------------------------
__global__ void __launch_bounds__(256)
agg2_kernel(const float* __restrict__ b2, const int* __restrict__ batch,
            float* out, int nrows)
{
    const int tid  = threadIdx.x;
    const int wid  = tid >> 5;
    const int lane = tid & 31;
    const int n0 = (blockIdx.x * 8 + wid) * 2;
    const int n1 = n0 + 1;
    const bool v0 = n0 < nrows, v1 = n1 < nrows;
    if (!v0) return;
    const bool active = (lane < 25);
    const int c4 = lane << 2;
    const float* gb = g_bufA;

    float4 A0 = make_float4(0.f,0.f,0.f,0.f), B0 = A0, A1 = A0, B1 = A0;
    int s0 = g_base[n0], nc0 = g_cnt[n0];
    int s1 = 0, nc1 = 0;
    if (active)
        A0 = *reinterpret_cast<const float4*>(&gb[(size_t)n0 * 128 + c4]);
    if (v1) {
        s1 = g_base[n1]; nc1 = g_cnt[n1];
        if (active)
            A1 = *reinterpret_cast<const float4*>(&gb[(size_t)n1 * 128 + c4]);
    }

    int mx = nc0 > nc1 ? nc0 : nc1;
    for (int i = 0; i < mx; i += 2) {
        if (i < nc0) {
            int sa = __ldg(&g_csrc[s0 + i]);
            if (active)
                add4(A0, *reinterpret_cast<const float4*>(&gb[(size_t)sa * 128 + c4]));
        }
        if (i + 1 < nc0) {
            int sb = __ldg(&g_csrc[s0 + i + 1]);
            if (active)
                add4(B0, *reinterpret_cast<const float4*>(&gb[(size_t)sb * 128 + c4]));
        }
        if (i < nc1) {
            int sa = __ldg(&g_csrc[s1 + i]);
            if (active)
                add4(A1, *reinterpret_cast<const float4*>(&gb[(size_t)sa * 128 + c4]));
        }
        if (i + 1 < nc1) {
            int sb = __ldg(&g_csrc[s1 + i + 1]);
            if (active)
                add4(B1, *reinterpret_cast<const float4*>(&gb[(size_t)sb * 128 + c4]));
        }
    }
    if (!active) return;
    add4(A0, B0); add4(A1, B1);

    float4 bb = *reinterpret_cast<const float4*>(&b2[c4]);
    {
        int g = __ldg(&batch[n0]);
        float di = g_dinv[n0];
        float* op = &out[(size_t)g * 100 + c4];
        atomicMaxF(op + 0, fmaf(A0.x, di, bb.x));
        atomicMaxF(op + 1, fmaf(A0.y, di, bb.y));
        atomicMaxF(op + 2, fmaf(A0.z, di, bb.z));
        atomicMaxF(op + 3, fmaf(A0.w, di, bb.w));
    }
    if (v1) {
        int g = __ldg(&batch[n1]);
        float di = g_dinv[n1];
        float* op = &out[(size_t)g * 100 + c4];
        atomicMaxF(op + 0, fmaf(A1.x, di, bb.x));
        atomicMaxF(op + 1, fmaf(A1.y, di, bb.y));
        atomicMaxF(op + 2, fmaf(A1.z, di, bb.z));
        atomicMaxF(op + 3, fmaf(A1.w, di, bb.w));
    }
}

// ---------------------------------------------------------------------------
extern "C" void kernel_launch(void* const* d_in, const int* in_sizes, int n_in,
                              void* d_out, int out_size)
{
    const float* atom  = (const float*)d_in[0];
    const int*   eidx  = (const int*)d_in[1];
    const int*   batch = (const int*)d_in[2];

    int base = 3;
    if (n_in >= 10 && in_sizes[3] == 1) base = 4;
    const float* W1    = (const float*)d_in[base + 0];
    const float* b1    = (const float*)d_in[base + 1];
    const float* gamma = (const float*)d_in[base + 2];
    const float* beta  = (const float*)d_in[base + 3];
    const float* W2    = (const float*)d_in[base + 4];
    const float* b2    = (const float*)d_in[base + 5];

    const int N = in_sizes[2];
    const int E = in_sizes[1] / 2;
    const int* src = eidx;
    const int* dst = eidx + E;
    float* out = (float*)d_out;

    const int SMEM_BYTES = 104448;  // 2*17408 + 2*34816
    static bool attr_done = false;
    if (!attr_done) {
        cudaFuncSetAttribute(gemm_mma_kernel<128, false, false>,
                             cudaFuncAttributeMaxDynamicSharedMemorySize, SMEM_BYTES);
        cudaFuncSetAttribute(gemm_mma_kernel<100, true, true>,
                             cudaFuncAttributeMaxDynamicSharedMemorySize, SMEM_BYTES);
        attr_done = true;
    }

    const int nScanBlocks = (N + 255) / 256;
    const int initN = (N > out_size) ? N : out_size;

    init_kernel<<<(initN + 255) / 256, 256>>>((unsigned int*)d_out, out_size, N);
    deg_kernel<<<(E + 255) / 256, 256>>>(dst, E);
    scan1_kernel<<<nScanBlocks, 256>>>(N);
    scan2_kernel<<<1, 1024>>>(nScanBlocks);
    scan3_kernel<<<nScanBlocks, 256>>>(N);
    scatter_kernel<<<(E + 255) / 256, 256>>>(src, dst, E);

    const int ablocks = (N + 15) / 16;   // 16 nodes per block (2 per warp)
    const int GGRID = 2 * NSM;           // 2 CTAs per SM

    // Layer 1
    gemm_mma_kernel<128, false, false><<<GGRID, 256, SMEM_BYTES>>>(atom, W1, N);
    agg1_kernel<<<ablocks, 256>>>(b1, N);
    bn_params_kernel<<<1, 128>>>(gamma, beta, 1.0f / (float)N);

    // Layer 2
    gemm_mma_kernel<100, true, true><<<GGRID, 256, SMEM_BYTES>>>(nullptr, W2, N);
    agg2_kernel<<<ablocks, 256>>>(b2, batch, out, N);
}